// round 1
// baseline (speedup 1.0000x reference)
#include <cuda_runtime.h>
#include <cstdint>

#define N_ATOMS 65536
#define N_BONDS 131072
#define ATOM_FDIM 133
#define BOND_TOTAL 147
#define BOND_FDIM 14
#define HIDDEN 256
#define MAX_NB 6
#define N_MOLS 2048
#define K_WH (HIDDEN + BOND_FDIM)      // 270
#define K_WO (ATOM_FDIM + HIDDEN)      // 389

// ---------------- scratch (static device globals; no allocation) ----------------
__device__ float g_inp[(size_t)N_ATOMS * HIDDEN];   // pre-relu Wi output
__device__ float g_msg[(size_t)N_ATOMS * HIDDEN];   // current message
__device__ float g_X[(size_t)N_ATOMS * K_WO];       // gathered GEMM input (max width 389)
__device__ float g_hid[(size_t)N_ATOMS * HIDDEN];   // atom_hiddens

// ---------------- SGEMM: C[M,256] = A[M,K] @ B[K,256] + bias, fused epilogues ----
// MODE 0: C0 = v; C1 = relu(v)                (inp + message init)
// MODE 1: C1 = relu(inp + v)                  (message update)
// MODE 2: C0 = relu(v)                        (atom_hiddens)
template <int MODE>
__global__ __launch_bounds__(256) void gemm_kernel(
    const float* __restrict__ A, int lda,
    const float* __restrict__ B,          // [K, 256] row-major
    const float* __restrict__ bias,       // [256]
    const float* __restrict__ inp,        // for MODE 1
    float* __restrict__ C0, float* __restrict__ C1,
    int K)
{
    constexpr int BM = 128, BN = 128, BK = 8;
    __shared__ float As[BK][BM];
    __shared__ float Bs[BK][BN];

    const int bx = blockIdx.x;            // N tile: 0 or 1
    const int by = blockIdx.y;            // M tile
    const int tid = threadIdx.x;
    const int tx = tid & 15;              // 16 x 16 thread grid
    const int ty = tid >> 4;

    float acc[8][8];
#pragma unroll
    for (int i = 0; i < 8; i++)
#pragma unroll
        for (int j = 0; j < 8; j++) acc[i][j] = 0.f;

    const float* Abase = A + (size_t)by * BM * lda;
    const float* Bbase = B + bx * BN;

    for (int k0 = 0; k0 < K; k0 += BK) {
        // load A tile (128 x 8) -> As[k][m]
#pragma unroll
        for (int i = 0; i < 4; i++) {
            int e = tid + i * 256;
            int r = e >> 3, c = e & 7;
            int kk = k0 + c;
            As[c][r] = (kk < K) ? Abase[(size_t)r * lda + kk] : 0.f;
        }
        // load B tile (8 x 128) -> Bs[k][n]
#pragma unroll
        for (int i = 0; i < 4; i++) {
            int e = tid + i * 256;
            int r = e >> 7, c = e & 127;
            int kk = k0 + r;
            Bs[r][c] = (kk < K) ? Bbase[(size_t)kk * HIDDEN + c] : 0.f;
        }
        __syncthreads();

#pragma unroll
        for (int k = 0; k < BK; k++) {
            float a[8], b[8];
#pragma unroll
            for (int i = 0; i < 8; i++) a[i] = As[k][ty * 8 + i];
#pragma unroll
            for (int j = 0; j < 8; j++) b[j] = Bs[k][tx * 8 + j];
#pragma unroll
            for (int i = 0; i < 8; i++)
#pragma unroll
                for (int j = 0; j < 8; j++) acc[i][j] += a[i] * b[j];
        }
        __syncthreads();
    }

    const int row0 = by * BM + ty * 8;
    const int col0 = bx * BN + tx * 8;
    float bv[8];
#pragma unroll
    for (int j = 0; j < 8; j++) bv[j] = bias[col0 + j];

#pragma unroll
    for (int i = 0; i < 8; i++) {
        const size_t base = (size_t)(row0 + i) * HIDDEN + col0;
#pragma unroll
        for (int j = 0; j < 8; j++) {
            float v = acc[i][j] + bv[j];
            if (MODE == 0) {
                C0[base + j] = v;
                C1[base + j] = fmaxf(v, 0.f);
            } else if (MODE == 1) {
                C1[base + j] = fmaxf(inp[base + j] + v, 0.f);
            } else {
                C0[base + j] = fmaxf(v, 0.f);
            }
        }
    }
}

// ---------------- gather for Wh input: X[:, 0:256]=sum msg[a2a], X[:,256:270]=sum fb_tail[a2b]
__global__ __launch_bounds__(256) void gather_h_kernel(
    const float* __restrict__ msg, const float* __restrict__ f_bonds,
    const int* __restrict__ a2a, const int* __restrict__ a2b,
    float* __restrict__ X)
{
    const int i = blockIdx.x;
    const int c = threadIdx.x;
    int n[MAX_NB];
#pragma unroll
    for (int j = 0; j < MAX_NB; j++) n[j] = a2a[i * MAX_NB + j];

    float acc = 0.f;
#pragma unroll
    for (int j = 0; j < MAX_NB; j++) acc += msg[(size_t)n[j] * HIDDEN + c];
    X[(size_t)i * K_WH + c] = acc;

    if (c < BOND_FDIM) {
        float bs = 0.f;
#pragma unroll
        for (int j = 0; j < MAX_NB; j++) {
            int b = a2b[i * MAX_NB + j];
            bs += f_bonds[(size_t)b * BOND_TOTAL + (BOND_TOTAL - BOND_FDIM) + c];
        }
        X[(size_t)i * K_WH + HIDDEN + c] = bs;
    }
}

// ---------------- gather for Wo input: X[:,0:133]=atom_features, X[:,133:389]=sum msg[a2a]
__global__ __launch_bounds__(256) void gather_o_kernel(
    const float* __restrict__ msg, const float* __restrict__ af,
    const int* __restrict__ a2a, float* __restrict__ X)
{
    const int i = blockIdx.x;
    const int c = threadIdx.x;
    if (c < ATOM_FDIM)
        X[(size_t)i * K_WO + c] = af[(size_t)i * ATOM_FDIM + c];

    int n[MAX_NB];
#pragma unroll
    for (int j = 0; j < MAX_NB; j++) n[j] = a2a[i * MAX_NB + j];
    float acc = 0.f;
#pragma unroll
    for (int j = 0; j < MAX_NB; j++) acc += msg[(size_t)n[j] * HIDDEN + c];
    X[(size_t)i * K_WO + ATOM_FDIM + c] = acc;
}

// ---------------- segment mean (segment_ids sorted; one block per molecule) ------
__global__ __launch_bounds__(256) void seg_mean_kernel(
    const float* __restrict__ hid, const int* __restrict__ seg,
    float* __restrict__ out)
{
    const int m = blockIdx.x;
    __shared__ int s_lo, s_hi;
    if (threadIdx.x == 0) {
        int lo = 0, hi = N_ATOMS;
        while (lo < hi) { int mid = (lo + hi) >> 1; if (seg[mid] < m) lo = mid + 1; else hi = mid; }
        s_lo = lo;
        hi = N_ATOMS;
        while (lo < hi) { int mid = (lo + hi) >> 1; if (seg[mid] < m + 1) lo = mid + 1; else hi = mid; }
        s_hi = lo;
    }
    __syncthreads();
    const int lo = s_lo, hi = s_hi, c = threadIdx.x;
    float acc = 0.f;
    for (int a = lo; a < hi; a++) acc += hid[(size_t)a * HIDDEN + c];
    const int cnt = hi - lo;
    out[(size_t)m * HIDDEN + c] = (cnt > 0) ? acc / (float)cnt : 0.f;
}

// ---------------- launch -----------------------------------------------------
extern "C" void kernel_launch(void* const* d_in, const int* in_sizes, int n_in,
                              void* d_out, int out_size)
{
    const float* atom_features = (const float*)d_in[0];   // [65536,133]
    const float* f_bonds       = (const float*)d_in[1];   // [131072,147]
    const int*   a2a           = (const int*)  d_in[2];   // [65536,6]
    const int*   a2b           = (const int*)  d_in[3];   // [65536,6]
    const int*   segment_ids   = (const int*)  d_in[4];   // [65536]
    const float* Wi            = (const float*)d_in[5];   // [133,256]
    const float* bi            = (const float*)d_in[6];
    const float* Wh            = (const float*)d_in[7];   // [270,256]
    const float* bh            = (const float*)d_in[8];
    const float* Wo            = (const float*)d_in[9];   // [389,256]
    const float* bo            = (const float*)d_in[10];
    float* out = (float*)d_out;                            // [2048,256]

    float* inp = nullptr; float* msg = nullptr; float* X = nullptr; float* hid = nullptr;
    cudaGetSymbolAddress((void**)&inp, g_inp);
    cudaGetSymbolAddress((void**)&msg, g_msg);
    cudaGetSymbolAddress((void**)&X,   g_X);
    cudaGetSymbolAddress((void**)&hid, g_hid);

    const dim3 ggrid(2, N_ATOMS / 128);

    // G1: inp = af @ Wi + bi ; msg = relu(inp)
    gemm_kernel<0><<<ggrid, 256>>>(atom_features, ATOM_FDIM, Wi, bi, nullptr, inp, msg, ATOM_FDIM);

    // message passing iterations (DEPTH-1 = 2)
    for (int d = 0; d < 2; d++) {
        gather_h_kernel<<<N_ATOMS, 256>>>(msg, f_bonds, a2a, a2b, X);
        gemm_kernel<1><<<ggrid, 256>>>(X, K_WH, Wh, bh, inp, nullptr, msg, K_WH);
    }

    // readout
    gather_o_kernel<<<N_ATOMS, 256>>>(msg, atom_features, a2a, X);
    gemm_kernel<2><<<ggrid, 256>>>(X, K_WO, Wo, bo, nullptr, hid, nullptr, K_WO);

    // segment mean
    seg_mean_kernel<<<N_MOLS, 256>>>(hid, segment_ids, out);
}

// round 8
// speedup vs baseline: 1.8697x; 1.8697x over previous
#include <cuda_runtime.h>
#include <cstdint>

#define N_ATOMS 65536
#define N_BONDS 131072
#define ATOM_FDIM 133
#define BOND_TOTAL 147
#define BOND_FDIM 14
#define HIDDEN 256
#define MAX_NB 6
#define N_MOLS 2048
#define XH_LD 272              // padded stride for Wh-input (270 -> 272)
#define XO_LD 392              // padded stride for Wo-input (389 -> 392, pad cols 133..135)

// ---------------- scratch (static device globals; no allocation) ----------------
__device__ float g_inp[(size_t)N_ATOMS * HIDDEN];
__device__ float g_msg[(size_t)N_ATOMS * HIDDEN];
__device__ float g_X[(size_t)N_ATOMS * XO_LD];
__device__ float g_hid[(size_t)N_ATOMS * HIDDEN];

// ---------------- async-copy helpers ----------------
__device__ __forceinline__ void cp_async4(uint32_t dst, const void* src, int sz) {
    asm volatile("cp.async.ca.shared.global [%0], [%1], 4, %2;\n" :: "r"(dst), "l"(src), "r"(sz));
}
__device__ __forceinline__ void cp_async16(uint32_t dst, const void* src, int sz) {
    asm volatile("cp.async.cg.shared.global [%0], [%1], 16, %2;\n" :: "r"(dst), "l"(src), "r"(sz));
}
__device__ __forceinline__ void cp_commit() { asm volatile("cp.async.commit_group;\n"); }
template <int N>
__device__ __forceinline__ void cp_wait() { asm volatile("cp.async.wait_group %0;\n" :: "n"(N)); }

// round-to-nearest fp32 -> tf32 (result in 32-bit container)
__device__ __forceinline__ uint32_t f2tf32(float x) {
    uint32_t r;
    asm("cvt.rna.tf32.f32 %0, %1;" : "=r"(r) : "f"(x));
    return r;
}

// m16n8k8 tf32 mma
__device__ __forceinline__ void mma_tf32(float* c, const uint32_t* a, const uint32_t* b) {
    asm("mma.sync.aligned.m16n8k8.row.col.f32.tf32.tf32.f32 "
        "{%0,%1,%2,%3}, {%4,%5,%6,%7}, {%8,%9}, {%0,%1,%2,%3};\n"
        : "+f"(c[0]), "+f"(c[1]), "+f"(c[2]), "+f"(c[3])
        : "r"(a[0]), "r"(a[1]), "r"(a[2]), "r"(a[3]), "r"(b[0]), "r"(b[1]));
}

// ---------------- tensor-core GEMM (split-TF32, fp32-accurate) ------------------
// C[M,256] = A[M,K] @ B'[*,256] + bias
// MODE 0: C0 = v; C1 = relu(v)
// MODE 1: C1 = relu(inp + v)
// MODE 2: C0 = relu(v), with B-row remap (A cols 133..135 are zero padding)
// Block tile 128x128, BK=16, 8 warps (warp tile 64x32), 2-stage cp.async pipeline.
// Each operand split hi/lo; acc += ah*bh + ah*bl + al*bh  (error ~2^-22).
template <int MODE, bool AVEC>
__global__ __launch_bounds__(256) void gemm_tc(
    const float* __restrict__ A, int lda, int K,
    const float* __restrict__ B, const float* __restrict__ bias,
    const float* __restrict__ inp,
    float* __restrict__ C0, float* __restrict__ C1)
{
    __shared__ __align__(16) float As[2][128 * 16];
    __shared__ __align__(16) float Bs[2][16 * 128];

    const int tid = threadIdx.x;
    const int lane = tid & 31;
    const int warp = tid >> 5;
    const int wm = (warp & 1) * 64;
    const int wn = (warp >> 1) * 32;
    const int bx = blockIdx.x;      // N half (0/1)
    const int by = blockIdx.y;      // M tile

    const uint32_t asBase = (uint32_t)__cvta_generic_to_shared(&As[0][0]);
    const uint32_t bsBase = (uint32_t)__cvta_generic_to_shared(&Bs[0][0]);

    // per-thread loader coords
    const int lm = tid >> 1;               // A tile row (0..127)
    const int lkc = (tid & 1) * 8;         // A tile col base (0 or 8)
    const int lr = tid >> 4;               // B tile row (k, 0..15)
    const int ln0 = (tid & 15) * 8;        // B tile col base

    const float* Arow = A + (size_t)(by * 128 + lm) * lda;

    auto load_chunk = [&](int chunk, int buf) {
        const int k0 = chunk * 16;
        const uint32_t aB = asBase + (uint32_t)buf * 128 * 16 * 4;
        const uint32_t bB = bsBase + (uint32_t)buf * 16 * 128 * 4;
        const int q = (lm >> 1) & 3;
        if (AVEC) {
#pragma unroll
            for (int h = 0; h < 2; h++) {
                const int c = lkc + h * 4;
                const int rem = (K - (k0 + c)) * 4;
                const int sz = rem <= 0 ? 0 : (rem >= 16 ? 16 : rem);
                const float* src = (rem <= 0) ? A : (Arow + k0 + c);
                const uint32_t dst = aB + (uint32_t)(lm * 16 + (c ^ (q << 2))) * 4;
                cp_async16(dst, src, sz);
            }
        } else {
#pragma unroll
            for (int j = 0; j < 8; j++) {
                const int c = lkc + j;
                const int ok = (k0 + c) < K;
                const float* src = ok ? (Arow + k0 + c) : A;
                const uint32_t dst = aB + (uint32_t)(lm * 16 + (c ^ (q << 2))) * 4;
                cp_async4(dst, src, ok ? 4 : 0);
            }
        }
        // B tile
        const int gk = k0 + lr;
        int br;
        if (MODE == 2) br = (gk < 136) ? (gk < 133 ? gk : 132) : (gk - 3);
        else br = gk;
        const int ok = gk < K;
        const float* bsrc = B + (size_t)(ok ? br : 0) * HIDDEN + bx * 128 + ln0;
        const int sw = (lr & 3) << 3;
#pragma unroll
        for (int h = 0; h < 2; h++) {
            const uint32_t dst = bB + (uint32_t)(lr * 128 + ((ln0 + h * 4) ^ sw)) * 4;
            cp_async16(dst, bsrc + h * 4, ok ? 16 : 0);
        }
    };

    float acc[4][4][4];
#pragma unroll
    for (int i = 0; i < 4; i++)
#pragma unroll
        for (int j = 0; j < 4; j++)
#pragma unroll
            for (int v = 0; v < 4; v++) acc[i][j][v] = 0.f;

    const int nchunks = (K + 15) / 16;

    load_chunk(0, 0);
    cp_commit();

    for (int ch = 0; ch < nchunks; ch++) {
        const int buf = ch & 1;
        if (ch + 1 < nchunks) {
            load_chunk(ch + 1, buf ^ 1);
            cp_commit();
            cp_wait<1>();
        } else {
            cp_wait<0>();
        }
        __syncthreads();

        const float* AsB = &As[buf][0];
        const float* BsB = &Bs[buf][0];
#pragma unroll
        for (int ks = 0; ks < 2; ks++) {
            uint32_t afh[4][4], afl[4][4];
            uint32_t bfh[4][2], bfl[4][2];
            const int kk = ks * 8 + (lane & 3);
#pragma unroll
            for (int mt = 0; mt < 4; mt++) {
                const int row = wm + mt * 16 + (lane >> 2);
                const int q = (row >> 1) & 3;
                const int kx0 = kk ^ (q << 2);
                const int kx1 = (kk + 4) ^ (q << 2);
                float v0 = AsB[row * 16 + kx0];
                float v1 = AsB[(row + 8) * 16 + kx0];
                float v2 = AsB[row * 16 + kx1];
                float v3 = AsB[(row + 8) * 16 + kx1];
                afh[mt][0] = f2tf32(v0); afl[mt][0] = f2tf32(v0 - __uint_as_float(afh[mt][0]));
                afh[mt][1] = f2tf32(v1); afl[mt][1] = f2tf32(v1 - __uint_as_float(afh[mt][1]));
                afh[mt][2] = f2tf32(v2); afl[mt][2] = f2tf32(v2 - __uint_as_float(afh[mt][2]));
                afh[mt][3] = f2tf32(v3); afl[mt][3] = f2tf32(v3 - __uint_as_float(afh[mt][3]));
            }
            const int sw = (kk & 3) << 3;
#pragma unroll
            for (int nt = 0; nt < 4; nt++) {
                const int n = (wn + nt * 8 + (lane >> 2)) ^ sw;
                float w0 = BsB[kk * 128 + n];
                float w1 = BsB[(kk + 4) * 128 + n];
                bfh[nt][0] = f2tf32(w0); bfl[nt][0] = f2tf32(w0 - __uint_as_float(bfh[nt][0]));
                bfh[nt][1] = f2tf32(w1); bfl[nt][1] = f2tf32(w1 - __uint_as_float(bfh[nt][1]));
            }
#pragma unroll
            for (int mt = 0; mt < 4; mt++)
#pragma unroll
                for (int nt = 0; nt < 4; nt++) {
                    mma_tf32(acc[mt][nt], afl[mt], bfh[nt]);   // small terms first
                    mma_tf32(acc[mt][nt], afh[mt], bfl[nt]);
                    mma_tf32(acc[mt][nt], afh[mt], bfh[nt]);
                }
        }
        __syncthreads();
    }

    // -------- epilogue --------
#pragma unroll
    for (int mt = 0; mt < 4; mt++) {
        const int r0 = by * 128 + wm + mt * 16 + (lane >> 2);
#pragma unroll
        for (int nt = 0; nt < 4; nt++) {
            const int co = bx * 128 + wn + nt * 8 + 2 * (lane & 3);
            const float2 bv = *reinterpret_cast<const float2*>(bias + co);
#pragma unroll
            for (int half = 0; half < 2; half++) {
                const int r = r0 + half * 8;
                const size_t base = (size_t)r * HIDDEN + co;
                float v0 = acc[mt][nt][half * 2 + 0] + bv.x;
                float v1 = acc[mt][nt][half * 2 + 1] + bv.y;
                if (MODE == 0) {
                    *reinterpret_cast<float2*>(C0 + base) = make_float2(v0, v1);
                    *reinterpret_cast<float2*>(C1 + base) =
                        make_float2(fmaxf(v0, 0.f), fmaxf(v1, 0.f));
                } else if (MODE == 1) {
                    const float2 iv = *reinterpret_cast<const float2*>(inp + base);
                    *reinterpret_cast<float2*>(C1 + base) =
                        make_float2(fmaxf(iv.x + v0, 0.f), fmaxf(iv.y + v1, 0.f));
                } else {
                    *reinterpret_cast<float2*>(C0 + base) =
                        make_float2(fmaxf(v0, 0.f), fmaxf(v1, 0.f));
                }
            }
        }
    }
}

// ---------------- gather for Wh input (stride XH_LD), float4-vectorized ----------
// 256 threads = 4 atoms x 64 lanes; each lane handles 4 hidden cols.
__global__ __launch_bounds__(256) void gather_h_kernel(
    const float* __restrict__ msg, const float* __restrict__ f_bonds,
    const int* __restrict__ a2a, const int* __restrict__ a2b,
    float* __restrict__ X)
{
    const int i = blockIdx.x * 4 + (threadIdx.x >> 6);
    const int c4 = threadIdx.x & 63;
    int n[MAX_NB];
#pragma unroll
    for (int j = 0; j < MAX_NB; j++) n[j] = a2a[i * MAX_NB + j];

    float4 acc = make_float4(0.f, 0.f, 0.f, 0.f);
#pragma unroll
    for (int j = 0; j < MAX_NB; j++) {
        const float4 v = *reinterpret_cast<const float4*>(msg + (size_t)n[j] * HIDDEN + c4 * 4);
        acc.x += v.x; acc.y += v.y; acc.z += v.z; acc.w += v.w;
    }
    *reinterpret_cast<float4*>(X + (size_t)i * XH_LD + c4 * 4) = acc;

    if (c4 < BOND_FDIM) {
        float bs = 0.f;
#pragma unroll
        for (int j = 0; j < MAX_NB; j++) {
            int b = a2b[i * MAX_NB + j];
            bs += f_bonds[(size_t)b * BOND_TOTAL + (BOND_TOTAL - BOND_FDIM) + c4];
        }
        X[(size_t)i * XH_LD + HIDDEN + c4] = bs;
    }
    if (c4 < 2) X[(size_t)i * XH_LD + 270 + c4] = 0.f;
}

// ---------------- gather for Wo input (stride XO_LD), float4-vectorized ----------
// af @ cols 0..132 (scalar), pad 133..135, msg-sum @ cols 136..391 (float4).
__global__ __launch_bounds__(256) void gather_o_kernel(
    const float* __restrict__ msg, const float* __restrict__ af,
    const int* __restrict__ a2a, float* __restrict__ X)
{
    const int i = blockIdx.x * 4 + (threadIdx.x >> 6);
    const int c4 = threadIdx.x & 63;

    for (int c = c4; c < ATOM_FDIM; c += 64)
        X[(size_t)i * XO_LD + c] = af[(size_t)i * ATOM_FDIM + c];
    if (c4 < 3)
        X[(size_t)i * XO_LD + ATOM_FDIM + c4] = 0.f;

    int n[MAX_NB];
#pragma unroll
    for (int j = 0; j < MAX_NB; j++) n[j] = a2a[i * MAX_NB + j];
    float4 acc = make_float4(0.f, 0.f, 0.f, 0.f);
#pragma unroll
    for (int j = 0; j < MAX_NB; j++) {
        const float4 v = *reinterpret_cast<const float4*>(msg + (size_t)n[j] * HIDDEN + c4 * 4);
        acc.x += v.x; acc.y += v.y; acc.z += v.z; acc.w += v.w;
    }
    *reinterpret_cast<float4*>(X + (size_t)i * XO_LD + 136 + c4 * 4) = acc;
}

// ---------------- segment mean (sorted segment_ids) ----------------
__global__ __launch_bounds__(256) void seg_mean_kernel(
    const float* __restrict__ hid, const int* __restrict__ seg,
    float* __restrict__ out)
{
    const int m = blockIdx.x;
    __shared__ int s_lo, s_hi;
    if (threadIdx.x == 0) {
        int lo = 0, hi = N_ATOMS;
        while (lo < hi) { int mid = (lo + hi) >> 1; if (seg[mid] < m) lo = mid + 1; else hi = mid; }
        s_lo = lo;
        hi = N_ATOMS;
        while (lo < hi) { int mid = (lo + hi) >> 1; if (seg[mid] < m + 1) lo = mid + 1; else hi = mid; }
        s_hi = lo;
    }
    __syncthreads();
    const int lo = s_lo, hi = s_hi, c = threadIdx.x;
    float accv = 0.f;
    for (int a = lo; a < hi; a++) accv += hid[(size_t)a * HIDDEN + c];
    const int cnt = hi - lo;
    out[(size_t)m * HIDDEN + c] = (cnt > 0) ? accv / (float)cnt : 0.f;
}

// ---------------- launch -----------------------------------------------------
extern "C" void kernel_launch(void* const* d_in, const int* in_sizes, int n_in,
                              void* d_out, int out_size)
{
    const float* atom_features = (const float*)d_in[0];
    const float* f_bonds       = (const float*)d_in[1];
    const int*   a2a           = (const int*)  d_in[2];
    const int*   a2b           = (const int*)  d_in[3];
    const int*   segment_ids   = (const int*)  d_in[4];
    const float* Wi            = (const float*)d_in[5];
    const float* bi            = (const float*)d_in[6];
    const float* Wh            = (const float*)d_in[7];
    const float* bh            = (const float*)d_in[8];
    const float* Wo            = (const float*)d_in[9];
    const float* bo            = (const float*)d_in[10];
    float* out = (float*)d_out;

    float *inp, *msg, *X, *hid;
    cudaGetSymbolAddress((void**)&inp, g_inp);
    cudaGetSymbolAddress((void**)&msg, g_msg);
    cudaGetSymbolAddress((void**)&X,   g_X);
    cudaGetSymbolAddress((void**)&hid, g_hid);

    const dim3 ggrid(2, N_ATOMS / 128);

    // G1: inp = af @ Wi + bi ; msg = relu(inp)   (lda=133 not 16B aligned -> scalar)
    gemm_tc<0, false><<<ggrid, 256>>>(atom_features, ATOM_FDIM, ATOM_FDIM, Wi, bi,
                                      nullptr, inp, msg);

    for (int d = 0; d < 2; d++) {
        gather_h_kernel<<<N_ATOMS / 4, 256>>>(msg, f_bonds, a2a, a2b, X);
        gemm_tc<1, true><<<ggrid, 256>>>(X, XH_LD, 270, Wh, bh, inp, nullptr, msg);
    }

    gather_o_kernel<<<N_ATOMS / 4, 256>>>(msg, atom_features, a2a, X);
    gemm_tc<2, true><<<ggrid, 256>>>(X, XO_LD, XO_LD, Wo, bo, nullptr, hid, nullptr);

    seg_mean_kernel<<<N_MOLS, 256>>>(hid, segment_ids, out);
}